// round 1
// baseline (speedup 1.0000x reference)
#include <cuda_runtime.h>
#include <math.h>

#define Nn 20000
#define Ee 320000
#define Hh 128
#define Kk 4
#define Ll 3
#define Bb 64
#define Cc 2

// output layout (flattened tuple, row-major each)
#define OUT_LOGITS 0        // [B,K,C]   512
#define OUT_HSTAB  512      // [B,K,H]   32768
#define OUT_HORIG  33280    // [B,H]     8192
#define OUT_NM     41472    // [N,K,1]   80000
#define OUT_EM     121472   // [E,K,1]   1280000

// ---------------- scratch (static device arrays; no runtime alloc) ----------------
__device__ float g_h0[Nn * Hh];
__device__ float g_h1[Nn * Hh];
__device__ float g_z [Nn * Hh];
__device__ float g_P [(size_t)Nn * Kk * 2 * Hh];     // [N][8][128]: (k,top/bot) blocks
__device__ float g_eh0[(size_t)Kk * Nn * Hh];
__device__ float g_eh1[(size_t)Kk * Nn * Hh];
__device__ float g_ez [(size_t)Kk * Nn * Hh];
__device__ int   g_deg[Nn];
__device__ int   g_off[Nn + 1];
__device__ int   g_cur[Nn];
__device__ int   g_csr_src[Ee];
__device__ int   g_csr_eid[Ee];
__device__ int   g_nwflag[Kk * Nn];
__device__ int   g_bstart[Bb + 1];

// ---------------- CSR build ----------------
__global__ void zero_prep() {
    int i = blockIdx.x * blockDim.x + threadIdx.x;
    if (i < Nn) g_deg[i] = 0;
    if (i < Kk * Nn) g_nwflag[i] = 0;
}

__global__ void hist_deg(const int* __restrict__ ei) {
    int e = blockIdx.x * blockDim.x + threadIdx.x;
    if (e < Ee) atomicAdd(&g_deg[ei[Ee + e]], 1);
}

__global__ void scan_kernel() {
    __shared__ int sh[1024];
    __shared__ int carry;
    int tid = threadIdx.x;
    if (tid == 0) carry = 0;
    __syncthreads();
    for (int base = 0; base < Nn; base += 1024) {
        int i = base + tid;
        int v = (i < Nn) ? g_deg[i] : 0;
        sh[tid] = v;
        __syncthreads();
        for (int ofs = 1; ofs < 1024; ofs <<= 1) {
            int t = (tid >= ofs) ? sh[tid - ofs] : 0;
            __syncthreads();
            sh[tid] += t;
            __syncthreads();
        }
        int incl = sh[tid];
        int excl = incl - v;
        int c = carry;
        if (i < Nn) { g_off[i] = c + excl; g_cur[i] = c + excl; }
        __syncthreads();
        if (tid == 1023) carry = c + incl;
        __syncthreads();
    }
    if (tid == 0) g_off[Nn] = carry;
}

__global__ void csr_fill(const int* __restrict__ ei) {
    int e = blockIdx.x * blockDim.x + threadIdx.x;
    if (e < Ee) {
        int d = ei[Ee + e];
        int p = atomicAdd(&g_cur[d], 1);
        g_csr_src[p] = ei[e];
        g_csr_eid[p] = e;
    }
}

__global__ void bstart_kernel(const int* __restrict__ batch) {
    int n = blockIdx.x * blockDim.x + threadIdx.x;
    if (n >= Nn) return;
    int bn = batch[n];
    if (n == 0) { for (int b = 0; b <= bn; b++) g_bstart[b] = 0; }
    else {
        int bp = batch[n - 1];
        for (int b = bp + 1; b <= bn; b++) g_bstart[b] = n;
    }
    if (n == Nn - 1) { for (int b = bn + 1; b <= Bb; b++) g_bstart[b] = Nn; }
}

// ---------------- aggregation (warp per node, CSR by dst) ----------------
__global__ void agg_enc(const float* __restrict__ hin, const float* __restrict__ epsp) {
    int w = (blockIdx.x * blockDim.x + threadIdx.x) >> 5;
    if (w >= Nn) return;
    int lane = threadIdx.x & 31;
    int col = lane * 4;
    int s = g_off[w], e = g_off[w + 1];
    float4 acc = make_float4(0.f, 0.f, 0.f, 0.f);
    for (int j = s; j < e; j++) {
        int sn = __ldg(&g_csr_src[j]);
        float4 v = *(const float4*)&hin[(size_t)sn * Hh + col];
        acc.x += v.x; acc.y += v.y; acc.z += v.z; acc.w += v.w;
    }
    float ep = 1.0f + __ldg(epsp);
    float4 hv = *(const float4*)&hin[(size_t)w * Hh + col];
    float4 z;
    z.x = fmaf(ep, hv.x, acc.x); z.y = fmaf(ep, hv.y, acc.y);
    z.z = fmaf(ep, hv.z, acc.z); z.w = fmaf(ep, hv.w, acc.w);
    *(float4*)&g_z[(size_t)w * Hh + col] = z;
}

__global__ void agg_exp(const float* __restrict__ hin, const float* __restrict__ epsp,
                        const float* __restrict__ em) {
    int k = blockIdx.z;
    int w = (blockIdx.x * blockDim.x + threadIdx.x) >> 5;
    if (w >= Nn) return;
    int lane = threadIdx.x & 31;
    int col = lane * 4;
    int s = g_off[w], e = g_off[w + 1];
    const float* hk = hin + (size_t)k * Nn * Hh;
    float4 acc = make_float4(0.f, 0.f, 0.f, 0.f);
    for (int j = s; j < e; j++) {
        int sn = __ldg(&g_csr_src[j]);
        int eid = __ldg(&g_csr_eid[j]);
        float wt = __ldg(&em[(size_t)eid * Kk + k]);
        if (wt != 0.0f) {
            float4 v = *(const float4*)&hk[(size_t)sn * Hh + col];
            acc.x = fmaf(wt, v.x, acc.x); acc.y = fmaf(wt, v.y, acc.y);
            acc.z = fmaf(wt, v.z, acc.z); acc.w = fmaf(wt, v.w, acc.w);
        }
    }
    float ep = 1.0f + __ldg(&epsp[k * Ll]);
    float4 hv = *(const float4*)&hk[(size_t)w * Hh + col];
    float4 z;
    z.x = fmaf(ep, hv.x, acc.x); z.y = fmaf(ep, hv.y, acc.y);
    z.z = fmaf(ep, hv.z, acc.z); z.w = fmaf(ep, hv.w, acc.w);
    *(float4*)&g_ez[((size_t)k * Nn + w) * Hh + col] = z;
}

// ---------------- fused 2-layer MLP: h = relu(relu(z@W1+b1)@W2+b2) ----------------
// block 256 threads, TM=64 rows, W1+W2+tile in dynamic smem (163840 B)
__global__ void __launch_bounds__(256, 1)
mlp2_kernel(const float* __restrict__ zin, float* __restrict__ hout,
            const float* __restrict__ W1, const float* __restrict__ b1,
            const float* __restrict__ W2, const float* __restrict__ b2,
            int M, int wstride, int bstride) {
    extern __shared__ float sm[];
    float* w1s = sm;          // 16384
    float* w2s = sm + 16384;  // 16384
    float* ts  = sm + 32768;  // 64*128 = 8192
    int k = blockIdx.z;
    const float* W1k = W1 + (size_t)k * wstride;
    const float* W2k = W2 + (size_t)k * wstride;
    const float* b1k = b1 + (size_t)k * bstride;
    const float* b2k = b2 + (size_t)k * bstride;
    const float* zk  = zin  + (size_t)k * M * Hh;
    float*       hk  = hout + (size_t)k * M * Hh;
    int tid = threadIdx.x;

    for (int i = tid * 4; i < 16384; i += 1024) {
        *(float4*)&w1s[i] = *(const float4*)&W1k[i];
        *(float4*)&w2s[i] = *(const float4*)&W2k[i];
    }
    int row0 = blockIdx.x * 64;
    for (int i = tid * 4; i < 8192; i += 1024) {
        int r = i >> 7, c = i & 127;
        int gr = row0 + r;
        float4 v = make_float4(0.f, 0.f, 0.f, 0.f);
        if (gr < M) v = *(const float4*)&zk[(size_t)gr * Hh + c];
        *(float4*)&ts[i] = v;
    }
    __syncthreads();

    int wr = tid >> 5, lane = tid & 31;
    int r0 = wr * 8, c0 = lane * 4;
    float acc[8][4];
    float bx = b1k[c0], by = b1k[c0 + 1], bz = b1k[c0 + 2], bw = b1k[c0 + 3];
#pragma unroll
    for (int i = 0; i < 8; i++) { acc[i][0] = bx; acc[i][1] = by; acc[i][2] = bz; acc[i][3] = bw; }
    for (int kk = 0; kk < 128; kk++) {
        float4 w = *(float4*)&w1s[kk * 128 + c0];
#pragma unroll
        for (int i = 0; i < 8; i++) {
            float zv = ts[(r0 + i) * 128 + kk];
            acc[i][0] = fmaf(zv, w.x, acc[i][0]);
            acc[i][1] = fmaf(zv, w.y, acc[i][1]);
            acc[i][2] = fmaf(zv, w.z, acc[i][2]);
            acc[i][3] = fmaf(zv, w.w, acc[i][3]);
        }
    }
    __syncthreads();
#pragma unroll
    for (int i = 0; i < 8; i++) {
        float4 h;
        h.x = fmaxf(acc[i][0], 0.f); h.y = fmaxf(acc[i][1], 0.f);
        h.z = fmaxf(acc[i][2], 0.f); h.w = fmaxf(acc[i][3], 0.f);
        *(float4*)&ts[(r0 + i) * 128 + c0] = h;
    }
    __syncthreads();

    bx = b2k[c0]; by = b2k[c0 + 1]; bz = b2k[c0 + 2]; bw = b2k[c0 + 3];
#pragma unroll
    for (int i = 0; i < 8; i++) { acc[i][0] = bx; acc[i][1] = by; acc[i][2] = bz; acc[i][3] = bw; }
    for (int kk = 0; kk < 128; kk++) {
        float4 w = *(float4*)&w2s[kk * 128 + c0];
#pragma unroll
        for (int i = 0; i < 8; i++) {
            float zv = ts[(r0 + i) * 128 + kk];
            acc[i][0] = fmaf(zv, w.x, acc[i][0]);
            acc[i][1] = fmaf(zv, w.y, acc[i][1]);
            acc[i][2] = fmaf(zv, w.z, acc[i][2]);
            acc[i][3] = fmaf(zv, w.w, acc[i][3]);
        }
    }
#pragma unroll
    for (int i = 0; i < 8; i++) {
        int gr = row0 + r0 + i;
        if (gr < M) {
            float4 h;
            h.x = fmaxf(acc[i][0], 0.f); h.y = fmaxf(acc[i][1], 0.f);
            h.z = fmaxf(acc[i][2], 0.f); h.w = fmaxf(acc[i][3], 0.f);
            *(float4*)&hk[(size_t)gr * Hh + c0] = h;
        }
    }
}

// ---------------- single-layer GEMM: P[:, ct*128:(ct+1)*128] = Z @ Wct (+ bias for top) ----------------
__global__ void __launch_bounds__(256, 1)
gemm1_kernel(const float* __restrict__ zin, const float* __restrict__ mW1,
             const float* __restrict__ mb1, int M) {
    extern __shared__ float sm[];
    float* ws = sm;           // 16384
    float* ts = sm + 16384;   // 8192
    int ct = blockIdx.y;      // 0..7 : ct = 2*k + half
    int kq = ct >> 1, half = ct & 1;
    const float* Wt = mW1 + (size_t)ct * 16384;
    int tid = threadIdx.x;
    for (int i = tid * 4; i < 16384; i += 1024)
        *(float4*)&ws[i] = *(const float4*)&Wt[i];
    int row0 = blockIdx.x * 64;
    for (int i = tid * 4; i < 8192; i += 1024) {
        int r = i >> 7, c = i & 127;
        int gr = row0 + r;
        float4 v = make_float4(0.f, 0.f, 0.f, 0.f);
        if (gr < M) v = *(const float4*)&zin[(size_t)gr * Hh + c];
        *(float4*)&ts[i] = v;
    }
    __syncthreads();
    int wr = tid >> 5, lane = tid & 31;
    int r0 = wr * 8, c0 = lane * 4;
    float acc[8][4];
    float bx = 0.f, by = 0.f, bz = 0.f, bw = 0.f;
    if (half == 0) {
        bx = mb1[kq * 128 + c0];     by = mb1[kq * 128 + c0 + 1];
        bz = mb1[kq * 128 + c0 + 2]; bw = mb1[kq * 128 + c0 + 3];
    }
#pragma unroll
    for (int i = 0; i < 8; i++) { acc[i][0] = bx; acc[i][1] = by; acc[i][2] = bz; acc[i][3] = bw; }
    for (int kk = 0; kk < 128; kk++) {
        float4 w = *(float4*)&ws[kk * 128 + c0];
#pragma unroll
        for (int i = 0; i < 8; i++) {
            float zv = ts[(r0 + i) * 128 + kk];
            acc[i][0] = fmaf(zv, w.x, acc[i][0]);
            acc[i][1] = fmaf(zv, w.y, acc[i][1]);
            acc[i][2] = fmaf(zv, w.z, acc[i][2]);
            acc[i][3] = fmaf(zv, w.w, acc[i][3]);
        }
    }
#pragma unroll
    for (int i = 0; i < 8; i++) {
        int gr = row0 + r0 + i;
        if (gr < M) {
            float4 h; h.x = acc[i][0]; h.y = acc[i][1]; h.z = acc[i][2]; h.w = acc[i][3];
            *(float4*)&g_P[(size_t)gr * 1024 + ct * 128 + c0] = h;
        }
    }
}

// ---------------- edge masks (warp per edge, all K experts) ----------------
__global__ void edge_mask_kernel(const int* __restrict__ ei, const float* __restrict__ u,
                                 const float* __restrict__ mW2, const float* __restrict__ mb2,
                                 float* __restrict__ dout) {
    __shared__ float w2s[Kk * Hh];
    int tid = threadIdx.x;
    for (int i = tid; i < Kk * Hh; i += blockDim.x) w2s[i] = mW2[i];
    __syncthreads();
    int wid = tid >> 5, lane = tid & 31;
    int e = blockIdx.x * 8 + wid;
    if (e >= Ee) return;
    int src = ei[e], dst = ei[Ee + e];
    const float* Ps = g_P + (size_t)src * 1024;
    const float* Pd = g_P + (size_t)dst * 1024 + 128;
    float r[4];
#pragma unroll
    for (int k = 0; k < 4; k++) {
        float4 pt = *(const float4*)&Ps[k * 256 + lane * 4];
        float4 pb = *(const float4*)&Pd[k * 256 + lane * 4];
        float4 wv = *(const float4*)&w2s[k * 128 + lane * 4];
        float a = fmaxf(pt.x + pb.x, 0.f) * wv.x + fmaxf(pt.y + pb.y, 0.f) * wv.y
                + fmaxf(pt.z + pb.z, 0.f) * wv.z + fmaxf(pt.w + pb.w, 0.f) * wv.w;
#pragma unroll
        for (int o = 16; o > 0; o >>= 1) a += __shfl_xor_sync(0xffffffffu, a, o);
        r[k] = a;
    }
    if (lane < 4) {
        int k = lane;
        float em = r[k] + mb2[k];
        float uu = u[(size_t)e * Kk + k];
        float gmb = -logf(-logf(uu + 1e-20f) + 1e-20f);
        float t = (em + gmb) / 0.1f;
        float ys = 1.0f / (1.0f + expf(-t));
        float yh = (ys > 0.5f) ? 1.0f : 0.0f;
        float eo = (yh + ys) - ys;
        dout[OUT_EM + (size_t)e * Kk + k] = eo;
        if (eo > 0.0f) {
            g_nwflag[k * Nn + src] = 1;
            g_nwflag[k * Nn + dst] = 1;
        }
    }
}

__global__ void nodemask_kernel(float* __restrict__ dout) {
    int n = blockIdx.x * blockDim.x + threadIdx.x;
    if (n >= Nn) return;
    float4 v;
    v.x = g_nwflag[0 * Nn + n] ? 1.f : 0.f;
    v.y = g_nwflag[1 * Nn + n] ? 1.f : 0.f;
    v.z = g_nwflag[2 * Nn + n] ? 1.f : 0.f;
    v.w = g_nwflag[3 * Nn + n] ? 1.f : 0.f;
    *(float4*)&dout[OUT_NM + (size_t)n * 4] = v;
}

__global__ void maskedx_kernel(const float* __restrict__ x) {
    size_t i = (size_t)blockIdx.x * blockDim.x + threadIdx.x;
    if (i >= (size_t)Kk * Nn * 32) return;
    size_t kn = i >> 5;
    int col = (int)(i & 31) * 4;
    size_t n = kn % Nn;
    float4 xv = *(const float4*)&x[n * Hh + col];
    if (!g_nwflag[kn]) xv = make_float4(0.f, 0.f, 0.f, 0.f);
    *(float4*)&g_eh0[kn * Hh + col] = xv;
}

// ---------------- pooling + head ----------------
__global__ void pool_kernel(float* __restrict__ dout) {
    int b = blockIdx.x, which = blockIdx.y, f = threadIdx.x;
    int s = g_bstart[b], e = g_bstart[b + 1];
    float denom = fmaxf((float)(e - s), 1.0f);
    const float* src;
    float* dp;
    if (which == Kk) { src = g_h0; dp = dout + OUT_HORIG + (size_t)b * Hh; }
    else {
        src = g_eh1 + (size_t)which * Nn * Hh;
        dp = dout + OUT_HSTAB + (size_t)b * (Kk * Hh) + which * Hh;
    }
    float acc = 0.f;
    for (int n = s; n < e; n++) acc += src[(size_t)n * Hh + f];
    dp[f] = acc / denom;
}

__global__ void head_kernel(const float* __restrict__ hW1, const float* __restrict__ hb1,
                            const float* __restrict__ hW2, const float* __restrict__ hb2,
                            float* __restrict__ dout) {
    int k = blockIdx.x, f = threadIdx.x;
    __shared__ float hid[Bb][Hh];
    const float* hs = dout + OUT_HSTAB;
    const float* W1 = hW1 + (size_t)k * Hh * Hh;
    for (int b = 0; b < Bb; b++) {
        float acc = hb1[k * Hh + f];
        for (int i = 0; i < Hh; i++)
            acc = fmaf(hs[(size_t)b * (Kk * Hh) + k * Hh + i], W1[i * Hh + f], acc);
        hid[b][f] = fmaxf(acc, 0.f);
    }
    __syncthreads();
    int b = f >> 1, c = f & 1;
    const float* W2 = hW2 + (size_t)k * Hh * Cc;
    float acc = hb2[k * Cc + c];
    for (int i = 0; i < Hh; i++)
        acc = fmaf(hid[b][i], W2[i * Cc + c], acc);
    dout[OUT_LOGITS + (size_t)b * (Kk * Cc) + k * Cc + c] = acc;
}

// ---------------- launch ----------------
extern "C" void kernel_launch(void* const* d_in, const int* in_sizes, int n_in,
                              void* d_out, int out_size) {
    const float* x       = (const float*)d_in[0];
    const int*   ei      = (const int*)d_in[1];
    const int*   batch   = (const int*)d_in[2];
    const float* u       = (const float*)d_in[3];
    const float* enc_W1  = (const float*)d_in[4];
    const float* enc_b1  = (const float*)d_in[5];
    const float* enc_W2  = (const float*)d_in[6];
    const float* enc_b2  = (const float*)d_in[7];
    const float* enc_eps = (const float*)d_in[8];
    const float* cls_W1  = (const float*)d_in[9];
    const float* cls_b1  = (const float*)d_in[10];
    const float* cls_W2  = (const float*)d_in[11];
    const float* cls_b2  = (const float*)d_in[12];
    const float* cls_eps = (const float*)d_in[13];
    const float* mask_W1 = (const float*)d_in[14];
    const float* mask_b1 = (const float*)d_in[15];
    const float* mask_W2 = (const float*)d_in[16];
    const float* mask_b2 = (const float*)d_in[17];
    const float* head_W1 = (const float*)d_in[18];
    const float* head_b1 = (const float*)d_in[19];
    const float* head_W2 = (const float*)d_in[20];
    const float* head_b2 = (const float*)d_in[21];
    float* out = (float*)d_out;

    cudaFuncSetAttribute(mlp2_kernel, cudaFuncAttributeMaxDynamicSharedMemorySize, 163840);
    cudaFuncSetAttribute(gemm1_kernel, cudaFuncAttributeMaxDynamicSharedMemorySize, 98304);

    float *ph0, *ph1, *pz, *peh0, *peh1, *pez;
    cudaGetSymbolAddress((void**)&ph0, g_h0);
    cudaGetSymbolAddress((void**)&ph1, g_h1);
    cudaGetSymbolAddress((void**)&pz, g_z);
    cudaGetSymbolAddress((void**)&peh0, g_eh0);
    cudaGetSymbolAddress((void**)&peh1, g_eh1);
    cudaGetSymbolAddress((void**)&pez, g_ez);

    // CSR + batch ranges
    zero_prep<<<(Kk * Nn + 255) / 256, 256>>>();
    hist_deg<<<(Ee + 255) / 256, 256>>>(ei);
    scan_kernel<<<1, 1024>>>();
    csr_fill<<<(Ee + 255) / 256, 256>>>(ei);
    bstart_kernel<<<(Nn + 255) / 256, 256>>>(batch);

    // encoder GIN stack
    const float* hin = x;
    float* hbuf[2] = { ph0, ph1 };
    for (int l = 0; l < Ll; l++) {
        agg_enc<<<(Nn * 32 + 255) / 256, 256>>>(hin, enc_eps + l);
        mlp2_kernel<<<dim3(313, 1, 1), 256, 163840>>>(
            pz, hbuf[l & 1],
            enc_W1 + (size_t)l * 16384, enc_b1 + l * 128,
            enc_W2 + (size_t)l * 16384, enc_b2 + l * 128,
            Nn, 0, 0);
        hin = hbuf[l & 1];
    }
    // Z = g_h0 (l=2 -> buf 0)

    // mask MLP layer-1 precompute: P = Z @ [Wtop|Wbot] per expert (+b1 on top)
    gemm1_kernel<<<dim3(313, 8), 256, 98304>>>(ph0, mask_W1, mask_b1, Nn);

    // per-edge mask logits + gumbel + masks
    edge_mask_kernel<<<Ee / 8, 256>>>(ei, u, mask_W2, mask_b2, out);
    nodemask_kernel<<<(Nn + 255) / 256, 256>>>(out);
    maskedx_kernel<<<(Kk * Nn * 32) / 256, 256>>>(x);

    // expert GIN stacks (all K batched via blockIdx.z)
    const float* ehin = peh0;
    float* ebuf[2] = { peh1, peh0 };
    for (int l = 0; l < Ll; l++) {
        agg_exp<<<dim3((Nn * 32 + 255) / 256, 1, Kk), 256>>>(ehin, cls_eps + l, out + OUT_EM);
        mlp2_kernel<<<dim3(313, 1, Kk), 256, 163840>>>(
            pez, ebuf[l & 1],
            cls_W1 + (size_t)l * 16384, cls_b1 + l * 128,
            cls_W2 + (size_t)l * 16384, cls_b2 + l * 128,
            Nn, Ll * 16384, Ll * 128);
        ehin = ebuf[l & 1];
    }
    // final expert h = g_eh1

    pool_kernel<<<dim3(Bb, Kk + 1), 128>>>(out);
    head_kernel<<<Kk, 128>>>(head_W1, head_b1, head_W2, head_b2, out);
}